// round 1
// baseline (speedup 1.0000x reference)
#include <cuda_runtime.h>
#include <cstdint>

#define N_NODES 10000
#define F_DIM   256
#define H_DIM   512
#define E_MAX   320000

// ---------------- scratch (device globals; no allocs allowed) ----------------
__device__ float g_xw[N_NODES * H_DIM];   // GEMM output buffer (reused both layers)
__device__ float g_h1[N_NODES * H_DIM];   // layer-1 activations
__device__ float g_dinv[N_NODES];
__device__ int   g_cnt[N_NODES];
__device__ int   g_off[N_NODES + 1];
__device__ int   g_cur[N_NODES];
__device__ int   g_csrc[E_MAX];
__device__ float g_cnorm[E_MAX];
__device__ int   g_is64;

// ---------------- edge dtype detection (int64 vs int32) ----------------
__global__ void k_detect(const void* eptr) {
    const unsigned int* w = (const unsigned int*)eptr;
    bool is64 = true;
    for (int i = 0; i < 32; i++) {
        if (w[2 * i + 1] != 0u) { is64 = false; break; }
    }
    g_is64 = is64 ? 1 : 0;
}

__device__ __forceinline__ int edge_dst(const void* eptr, int e, int E) {
    if (g_is64) return (int)((const long long*)eptr)[(size_t)E + e];
    return ((const int*)eptr)[(size_t)E + e];
}
__device__ __forceinline__ void edge_sd(const void* eptr, int e, int E, int& s, int& d) {
    if (g_is64) {
        const long long* p = (const long long*)eptr;
        s = (int)p[e]; d = (int)p[(size_t)E + e];
    } else {
        const int* p = (const int*)eptr;
        s = p[e]; d = p[(size_t)E + e];
    }
}

// ---------------- graph preprocessing ----------------
__global__ void k_zero() {
    int i = blockIdx.x * blockDim.x + threadIdx.x;
    if (i < N_NODES) { g_cnt[i] = 0; g_cur[i] = 0; }
}

__global__ void k_count(const void* eptr, int E) {
    int e = blockIdx.x * blockDim.x + threadIdx.x;
    if (e >= E) return;
    atomicAdd(&g_cnt[edge_dst(eptr, e, E)], 1);
}

__global__ void k_dinv() {
    int i = blockIdx.x * blockDim.x + threadIdx.x;
    if (i < N_NODES) g_dinv[i] = rsqrtf((float)g_cnt[i] + 1.0f);
}

// single-block exclusive scan over g_cnt -> g_off
__global__ void k_scan() {
    __shared__ int sdata[1024];
    __shared__ int carry;
    int tid = threadIdx.x;
    if (tid == 0) { carry = 0; g_off[0] = 0; }
    for (int base = 0; base < N_NODES; base += 1024) {
        __syncthreads();
        int i = base + tid;
        int v = (i < N_NODES) ? g_cnt[i] : 0;
        sdata[tid] = v;
        __syncthreads();
        #pragma unroll
        for (int ofs = 1; ofs < 1024; ofs <<= 1) {
            int t = (tid >= ofs) ? sdata[tid - ofs] : 0;
            __syncthreads();
            sdata[tid] += t;
            __syncthreads();
        }
        int inc = sdata[tid];
        int total = sdata[1023];
        if (i < N_NODES) g_off[i + 1] = carry + inc;
        __syncthreads();
        if (tid == 0) carry += total;
    }
}

__global__ void k_scatter(const void* eptr, int E) {
    int e = blockIdx.x * blockDim.x + threadIdx.x;
    if (e >= E) return;
    int s, d;
    edge_sd(eptr, e, E, s, d);
    int pos = g_off[d] + atomicAdd(&g_cur[d], 1);
    g_csrc[pos] = s;
    g_cnorm[pos] = g_dinv[s] * g_dinv[d];
}

// ---------------- fp32 tiled SIMT GEMM: C[M,Nc] = A[M,K] @ B[K,Nc] ----------------
// BM=BN=128, BK=8, TM=TN=8, 256 threads. C is always g_xw.
__global__ void __launch_bounds__(256) k_sgemm(const float* __restrict__ Aext,
                                               const float* __restrict__ B,
                                               int M, int Nc, int K, int useH1) {
    const float* __restrict__ A = useH1 ? g_h1 : Aext;
    float* __restrict__ C = g_xw;

    __shared__ float As[8][128];
    __shared__ float Bs[8][128];

    int tid = threadIdx.x;
    int block_row = blockIdx.x * 128;
    int block_col = blockIdx.y * 128;

    int arow = tid >> 1;          // 0..127
    int acol = (tid & 1) * 4;     // 0 or 4
    int brow = tid >> 5;          // 0..7
    int bcol = (tid & 31) * 4;    // 0..124

    int ty = tid / 16, tx = tid % 16;
    int row0 = ty * 8, col0 = tx * 8;

    float acc[8][8];
    #pragma unroll
    for (int i = 0; i < 8; i++)
        #pragma unroll
        for (int j = 0; j < 8; j++) acc[i][j] = 0.0f;

    for (int k0 = 0; k0 < K; k0 += 8) {
        float4 av;
        int gr = block_row + arow;
        if (gr < M) av = *(const float4*)(A + (size_t)gr * K + k0 + acol);
        else        av = make_float4(0.f, 0.f, 0.f, 0.f);
        As[acol + 0][arow] = av.x;
        As[acol + 1][arow] = av.y;
        As[acol + 2][arow] = av.z;
        As[acol + 3][arow] = av.w;

        float4 bv = *(const float4*)(B + (size_t)(k0 + brow) * Nc + block_col + bcol);
        *(float4*)&Bs[brow][bcol] = bv;
        __syncthreads();

        #pragma unroll
        for (int k = 0; k < 8; k++) {
            float4 a0 = *(const float4*)&As[k][row0];
            float4 a1 = *(const float4*)&As[k][row0 + 4];
            float4 b0 = *(const float4*)&Bs[k][col0];
            float4 b1 = *(const float4*)&Bs[k][col0 + 4];
            float ar[8] = {a0.x, a0.y, a0.z, a0.w, a1.x, a1.y, a1.z, a1.w};
            float br[8] = {b0.x, b0.y, b0.z, b0.w, b1.x, b1.y, b1.z, b1.w};
            #pragma unroll
            for (int i = 0; i < 8; i++)
                #pragma unroll
                for (int j = 0; j < 8; j++)
                    acc[i][j] = fmaf(ar[i], br[j], acc[i][j]);
        }
        __syncthreads();
    }

    #pragma unroll
    for (int i = 0; i < 8; i++) {
        int r = block_row + row0 + i;
        if (r < M) {
            float4 c0 = make_float4(acc[i][0], acc[i][1], acc[i][2], acc[i][3]);
            float4 c1 = make_float4(acc[i][4], acc[i][5], acc[i][6], acc[i][7]);
            *(float4*)(C + (size_t)r * Nc + block_col + col0) = c0;
            *(float4*)(C + (size_t)r * Nc + block_col + col0 + 4) = c1;
        }
    }
}

// ---------------- CSR aggregation (+bias+relu); optionally fuse max pool ----------------
// One block per dst node; H/4 threads, float4 per thread. Reads g_xw.
template <int H, bool FUSE_MAX>
__global__ void k_aggregate(const float* __restrict__ bias, float* __restrict__ out) {
    int n = blockIdx.x;
    int tid = threadIdx.x;
    int c = tid * 4;

    __shared__ int   s_src[64];
    __shared__ float s_w[64];

    float4 acc = make_float4(0.f, 0.f, 0.f, 0.f);
    int s = g_off[n], e = g_off[n + 1];

    for (int base = s; base < e; base += 64) {
        int cnt = min(64, e - base);
        __syncthreads();
        if (tid < cnt) {
            s_src[tid] = g_csrc[base + tid];
            s_w[tid]   = g_cnorm[base + tid];
        }
        __syncthreads();
        for (int i = 0; i < cnt; i++) {
            const float4 v = *(const float4*)(g_xw + (size_t)s_src[i] * H + c);
            float w = s_w[i];
            acc.x = fmaf(w, v.x, acc.x);
            acc.y = fmaf(w, v.y, acc.y);
            acc.z = fmaf(w, v.z, acc.z);
            acc.w = fmaf(w, v.w, acc.w);
        }
    }

    // self-loop: dinv_i^2 * xw_i
    float di = g_dinv[n];
    float w = di * di;
    const float4 v = *(const float4*)(g_xw + (size_t)n * H + c);
    acc.x = fmaf(w, v.x, acc.x);
    acc.y = fmaf(w, v.y, acc.y);
    acc.z = fmaf(w, v.z, acc.z);
    acc.w = fmaf(w, v.w, acc.w);

    const float4 b = *(const float4*)(bias + c);
    acc.x = fmaxf(acc.x + b.x, 0.f);
    acc.y = fmaxf(acc.y + b.y, 0.f);
    acc.z = fmaxf(acc.z + b.z, 0.f);
    acc.w = fmaxf(acc.w + b.w, 0.f);

    if (FUSE_MAX) {
        // post-ReLU values are >= 0, so int ordering == float ordering
        int* o = (int*)out;
        atomicMax(o + c + 0, __float_as_int(acc.x));
        atomicMax(o + c + 1, __float_as_int(acc.y));
        atomicMax(o + c + 2, __float_as_int(acc.z));
        atomicMax(o + c + 3, __float_as_int(acc.w));
    } else {
        *(float4*)(g_h1 + (size_t)n * H + c) = acc;
    }
}

__global__ void k_init_out(float* out) { out[threadIdx.x] = 0.0f; }

// ---------------- launch ----------------
extern "C" void kernel_launch(void* const* d_in, const int* in_sizes, int n_in,
                              void* d_out, int out_size) {
    const float* x  = (const float*)d_in[0];
    const void*  ei = d_in[1];
    const float* W1 = (const float*)d_in[2];
    const float* b1 = (const float*)d_in[3];
    const float* W2 = (const float*)d_in[4];
    const float* b2 = (const float*)d_in[5];
    float* out = (float*)d_out;

    int E = in_sizes[1] / 2;

    k_detect<<<1, 1>>>(ei);
    k_zero<<<(N_NODES + 255) / 256, 256>>>();
    k_count<<<(E + 255) / 256, 256>>>(ei, E);
    k_dinv<<<(N_NODES + 255) / 256, 256>>>();
    k_scan<<<1, 1024>>>();
    k_scatter<<<(E + 255) / 256, 256>>>(ei, E);

    // layer 1: xw = x @ W1  (10000x256 @ 256x512)
    dim3 g1((N_NODES + 127) / 128, H_DIM / 128);
    k_sgemm<<<g1, 256>>>(x, W1, N_NODES, H_DIM, F_DIM, 0);
    // aggregate + b1 + relu -> g_h1
    k_aggregate<H_DIM, false><<<N_NODES, H_DIM / 4>>>(b1, nullptr);

    // layer 2: xw = h1 @ W2  (10000x512 @ 512x256)
    dim3 g2((N_NODES + 127) / 128, F_DIM / 128);
    k_sgemm<<<g2, 256>>>(nullptr, W2, N_NODES, F_DIM, H_DIM, 1);

    // aggregate + b2 + relu, fused global max pool -> out (1x256)
    k_init_out<<<1, F_DIM>>>(out);
    k_aggregate<F_DIM, true><<<N_NODES, F_DIM / 4>>>(b2, out);
}

// round 3
// speedup vs baseline: 1.2739x; 1.2739x over previous
#include <cuda_runtime.h>
#include <cstdint>

#define N_NODES 10000
#define F_DIM   256
#define H_DIM   512
#define E_MAX   320000

// ---------------- scratch (device globals; no allocs allowed) ----------------
__device__ float g_ax[N_NODES * F_DIM];   // aggregated X (layer-1 agg-first)
__device__ float g_h1[N_NODES * H_DIM];   // layer-1 activations (gemm1 out)
__device__ float g_c2[N_NODES * F_DIM];   // gemm2 out (pre-aggregation)
__device__ float g_dinv[N_NODES];
__device__ int   g_cnt[N_NODES];
__device__ int   g_off[N_NODES + 1];
__device__ int   g_cur[N_NODES];
__device__ int   g_csrc[E_MAX];
__device__ float g_cnorm[E_MAX];
__device__ int   g_is64;

// ---------------- edge dtype detection (int64 vs int32) ----------------
__global__ void k_detect(const void* eptr) {
    const unsigned int* w = (const unsigned int*)eptr;
    bool is64 = true;
    for (int i = 0; i < 32; i++) {
        if (w[2 * i + 1] != 0u) { is64 = false; break; }
    }
    g_is64 = is64 ? 1 : 0;
}

__device__ __forceinline__ int edge_dst(const void* eptr, int e, int E) {
    if (g_is64) return (int)((const long long*)eptr)[(size_t)E + e];
    return ((const int*)eptr)[(size_t)E + e];
}
__device__ __forceinline__ void edge_sd(const void* eptr, int e, int E, int& s, int& d) {
    if (g_is64) {
        const long long* p = (const long long*)eptr;
        s = (int)p[e]; d = (int)p[(size_t)E + e];
    } else {
        const int* p = (const int*)eptr;
        s = p[e]; d = p[(size_t)E + e];
    }
}

// ---------------- graph preprocessing ----------------
__global__ void k_zero(float* out) {
    int i = blockIdx.x * blockDim.x + threadIdx.x;
    if (i < N_NODES) { g_cnt[i] = 0; g_cur[i] = 0; }
    if (blockIdx.x == 0 && threadIdx.x < F_DIM) out[threadIdx.x] = 0.0f;
}

__global__ void k_count(const void* eptr, int E) {
    int e = blockIdx.x * blockDim.x + threadIdx.x;
    if (e >= E) return;
    atomicAdd(&g_cnt[edge_dst(eptr, e, E)], 1);
}

// single-block exclusive scan over g_cnt -> g_off, fused dinv
__global__ void k_scan() {
    __shared__ int sdata[1024];
    __shared__ int carry;
    int tid = threadIdx.x;
    if (tid == 0) { carry = 0; g_off[0] = 0; }
    for (int base = 0; base < N_NODES; base += 1024) {
        __syncthreads();
        int i = base + tid;
        int v = 0;
        if (i < N_NODES) {
            v = g_cnt[i];
            g_dinv[i] = rsqrtf((float)v + 1.0f);
        }
        sdata[tid] = v;
        __syncthreads();
        #pragma unroll
        for (int ofs = 1; ofs < 1024; ofs <<= 1) {
            int t = (tid >= ofs) ? sdata[tid - ofs] : 0;
            __syncthreads();
            sdata[tid] += t;
            __syncthreads();
        }
        int inc = sdata[tid];
        int total = sdata[1023];
        if (i < N_NODES) g_off[i + 1] = carry + inc;
        __syncthreads();
        if (tid == 0) carry += total;
    }
}

__global__ void k_scatter(const void* eptr, int E) {
    int e = blockIdx.x * blockDim.x + threadIdx.x;
    if (e >= E) return;
    int s, d;
    edge_sd(eptr, e, E, s, d);
    int pos = g_off[d] + atomicAdd(&g_cur[d], 1);
    g_csrc[pos] = s;
    g_cnorm[pos] = g_dinv[s] * g_dinv[d];
}

// ---------------- TF32 mma.sync GEMM ----------------
// C[M,Nc] = A[M,K] @ B[K,Nc]; block tile 128x128, K-step 32, 8 warps (4m x 2n),
// warp tile 32x64 via m16n8k8 tf32 mma. mode==1: A=g_ax, C=g_h1, +bias+relu.
// mode==2: A=g_h1, C=g_c2, plain.
#define AS_STRIDE 36
#define BS_STRIDE 136

__device__ __forceinline__ uint32_t f2tf32(float f) {
    uint32_t u;
    asm("cvt.rna.tf32.f32 %0, %1;" : "=r"(u) : "f"(f));
    return u;
}

__device__ __forceinline__ void mma_tf32(float* d, const uint32_t* a, const uint32_t* b) {
    asm volatile(
        "mma.sync.aligned.m16n8k8.row.col.f32.tf32.tf32.f32 "
        "{%0,%1,%2,%3},{%4,%5,%6,%7},{%8,%9},{%0,%1,%2,%3};"
        : "+f"(d[0]), "+f"(d[1]), "+f"(d[2]), "+f"(d[3])
        : "r"(a[0]), "r"(a[1]), "r"(a[2]), "r"(a[3]), "r"(b[0]), "r"(b[1]));
}

__global__ void __launch_bounds__(256) k_gemm(const float* __restrict__ Bw,
                                              const float* __restrict__ bias,
                                              int M, int Nc, int K, int mode) {
    const float* __restrict__ A = (mode == 1) ? g_ax : g_h1;
    float* __restrict__ C = (mode == 1) ? g_h1 : g_c2;

    __shared__ uint32_t As[128 * AS_STRIDE];
    __shared__ uint32_t Bs[32 * BS_STRIDE];

    const int tid = threadIdx.x;
    const int lane = tid & 31;
    const int warp = tid >> 5;
    const int wm = warp >> 1;        // 0..3
    const int wn = warp & 1;         // 0..1
    const int bm = blockIdx.x * 128;
    const int bn = blockIdx.y * 128;

    // gmem->smem mappings
    const int arow = tid >> 1;                 // 0..127
    const int ak0  = (tid & 1) * 16;           // 0 or 16 (4 float4 each)
    const int bkr  = tid >> 3;                 // 0..31
    const int bn0  = (tid & 7) * 4;            // 0..28 (float4, +32 per j)

    // fragment bases
    const int g = lane >> 2, c = lane & 3;
    const int a_base = (wm * 32 + g) * AS_STRIDE + c;
    const int b_base = c * BS_STRIDE + wn * 64 + g;

    float acc[2][8][4];
    #pragma unroll
    for (int mi = 0; mi < 2; mi++)
        #pragma unroll
        for (int ni = 0; ni < 8; ni++)
            #pragma unroll
            for (int j = 0; j < 4; j++) acc[mi][ni][j] = 0.0f;

    const int T = K / 32;
    float4 aS[4], bS[4];

    // prologue: load tile 0
    {
        const int gr = bm + arow;
        #pragma unroll
        for (int j = 0; j < 4; j++) {
            if (gr < M) aS[j] = *(const float4*)(A + (size_t)gr * K + ak0 + 4 * j);
            else        aS[j] = make_float4(0.f, 0.f, 0.f, 0.f);
            bS[j] = *(const float4*)(Bw + (size_t)bkr * Nc + bn + bn0 + 32 * j);
        }
    }

    for (int kt = 0; kt < T; kt++) {
        // cvt + store staged tile to smem
        #pragma unroll
        for (int j = 0; j < 4; j++) {
            uint32_t* pa = &As[arow * AS_STRIDE + ak0 + 4 * j];
            pa[0] = f2tf32(aS[j].x); pa[1] = f2tf32(aS[j].y);
            pa[2] = f2tf32(aS[j].z); pa[3] = f2tf32(aS[j].w);
            uint32_t* pb = &Bs[bkr * BS_STRIDE + bn0 + 32 * j];
            pb[0] = f2tf32(bS[j].x); pb[1] = f2tf32(bS[j].y);
            pb[2] = f2tf32(bS[j].z); pb[3] = f2tf32(bS[j].w);
        }
        __syncthreads();

        // prefetch next tile into regs (hidden under compute)
        if (kt + 1 < T) {
            const int k0 = (kt + 1) * 32;
            const int gr = bm + arow;
            #pragma unroll
            for (int j = 0; j < 4; j++) {
                if (gr < M) aS[j] = *(const float4*)(A + (size_t)gr * K + k0 + ak0 + 4 * j);
                else        aS[j] = make_float4(0.f, 0.f, 0.f, 0.f);
                bS[j] = *(const float4*)(Bw + (size_t)(k0 + bkr) * Nc + bn + bn0 + 32 * j);
            }
        }

        // compute 4 x k8 steps
        #pragma unroll
        for (int k8 = 0; k8 < 4; k8++) {
            uint32_t af[2][4], bf[8][2];
            const int ak = a_base + k8 * 8;
            #pragma unroll
            for (int mi = 0; mi < 2; mi++) {
                const int o = ak + mi * (16 * AS_STRIDE);
                af[mi][0] = As[o];
                af[mi][1] = As[o + 8 * AS_STRIDE];
                af[mi][2] = As[o + 4];
                af[mi][3] = As[o + 8 * AS_STRIDE + 4];
            }
            const int bk = b_base + k8 * 8 * BS_STRIDE;
            #pragma unroll
            for (int ni = 0; ni < 8; ni++) {
                bf[ni][0] = Bs[bk + ni * 8];
                bf[ni][1] = Bs[bk + 4 * BS_STRIDE + ni * 8];
            }
            #pragma unroll
            for (int mi = 0; mi < 2; mi++)
                #pragma unroll
                for (int ni = 0; ni < 8; ni++)
                    mma_tf32(acc[mi][ni], af[mi], bf[ni]);
        }
        __syncthreads();
    }

    // epilogue
    const bool relu = (mode == 1);
    #pragma unroll
    for (int mi = 0; mi < 2; mi++) {
        const int r0 = bm + wm * 32 + mi * 16 + g;
        const int r1 = r0 + 8;
        #pragma unroll
        for (int ni = 0; ni < 8; ni++) {
            const int col = bn + wn * 64 + ni * 8 + 2 * c;
            float v0 = acc[mi][ni][0], v1 = acc[mi][ni][1];
            float v2 = acc[mi][ni][2], v3 = acc[mi][ni][3];
            if (relu) {
                const float bb0 = bias[col], bb1 = bias[col + 1];
                v0 = fmaxf(v0 + bb0, 0.f); v1 = fmaxf(v1 + bb1, 0.f);
                v2 = fmaxf(v2 + bb0, 0.f); v3 = fmaxf(v3 + bb1, 0.f);
            }
            if (r0 < M) *(float2*)(C + (size_t)r0 * Nc + col) = make_float2(v0, v1);
            if (r1 < M) *(float2*)(C + (size_t)r1 * Nc + col) = make_float2(v2, v3);
        }
    }
}

// ---------------- CSR aggregation on 256 features ----------------
// MODE 0: g_ax[n] = sum norm*xsrc[s] + dinv^2*xsrc[n]          (layer-1, pre-GEMM)
// MODE 1: src = g_c2 (device-side!); fused +bias, relu, atomic max into out(256)
template <int MODE>
__global__ void k_aggregate(const float* __restrict__ xsrc,
                            const float* __restrict__ bias,
                            float* __restrict__ out) {
    // device-side source selection — NEVER pass a __device__ symbol from host
    const float* __restrict__ src = (MODE == 0) ? xsrc : (const float*)g_c2;

    const int n = blockIdx.x;
    const int tid = threadIdx.x;
    const int ccol = tid * 4;

    __shared__ int   s_src[64];
    __shared__ float s_w[64];

    float4 acc = make_float4(0.f, 0.f, 0.f, 0.f);
    const int s = g_off[n], e = g_off[n + 1];

    for (int base = s; base < e; base += 64) {
        const int cnt = min(64, e - base);
        __syncthreads();
        if (tid < cnt) {
            s_src[tid] = g_csrc[base + tid];
            s_w[tid]   = g_cnorm[base + tid];
        }
        __syncthreads();
        for (int i = 0; i < cnt; i++) {
            const float4 v = *(const float4*)(src + (size_t)s_src[i] * F_DIM + ccol);
            const float w = s_w[i];
            acc.x = fmaf(w, v.x, acc.x);
            acc.y = fmaf(w, v.y, acc.y);
            acc.z = fmaf(w, v.z, acc.z);
            acc.w = fmaf(w, v.w, acc.w);
        }
    }

    // self-loop
    const float di = g_dinv[n];
    const float w = di * di;
    const float4 v = *(const float4*)(src + (size_t)n * F_DIM + ccol);
    acc.x = fmaf(w, v.x, acc.x);
    acc.y = fmaf(w, v.y, acc.y);
    acc.z = fmaf(w, v.z, acc.z);
    acc.w = fmaf(w, v.w, acc.w);

    if (MODE == 0) {
        *(float4*)(g_ax + (size_t)n * F_DIM + ccol) = acc;
    } else {
        const float4 b = *(const float4*)(bias + ccol);
        acc.x = fmaxf(acc.x + b.x, 0.f);
        acc.y = fmaxf(acc.y + b.y, 0.f);
        acc.z = fmaxf(acc.z + b.z, 0.f);
        acc.w = fmaxf(acc.w + b.w, 0.f);
        // post-ReLU values >= 0, so int ordering == float ordering
        int* o = (int*)out;
        atomicMax(o + ccol + 0, __float_as_int(acc.x));
        atomicMax(o + ccol + 1, __float_as_int(acc.y));
        atomicMax(o + ccol + 2, __float_as_int(acc.z));
        atomicMax(o + ccol + 3, __float_as_int(acc.w));
    }
}

// ---------------- launch ----------------
extern "C" void kernel_launch(void* const* d_in, const int* in_sizes, int n_in,
                              void* d_out, int out_size) {
    const float* x  = (const float*)d_in[0];
    const void*  ei = d_in[1];
    const float* W1 = (const float*)d_in[2];
    const float* b1 = (const float*)d_in[3];
    const float* W2 = (const float*)d_in[4];
    const float* b2 = (const float*)d_in[5];
    float* out = (float*)d_out;

    const int E = in_sizes[1] / 2;

    k_detect<<<1, 1>>>(ei);
    k_zero<<<(N_NODES + 255) / 256, 256>>>(out);
    k_count<<<(E + 255) / 256, 256>>>(ei, E);
    k_scan<<<1, 1024>>>();
    k_scatter<<<(E + 255) / 256, 256>>>(ei, E);

    // layer 1: aggregate-first (linearity: A(XW) = (AX)W)
    k_aggregate<0><<<N_NODES, F_DIM / 4>>>(x, nullptr, nullptr);
    // h1 = relu((AX) @ W1 + b1): 10000x256 @ 256x512
    dim3 g1((N_NODES + 127) / 128, H_DIM / 128);
    k_gemm<<<g1, 256>>>(W1, b1, N_NODES, H_DIM, F_DIM, 1);

    // layer 2: c2 = h1 @ W2: 10000x512 @ 512x256
    dim3 g2((N_NODES + 127) / 128, F_DIM / 128);
    k_gemm<<<g2, 256>>>(W2, nullptr, N_NODES, F_DIM, H_DIM, 2);

    // aggregate + b2 + relu + fused global max pool -> out (1x256)
    k_aggregate<1><<<N_NODES, F_DIM / 4>>>(nullptr, b2, out);
}

// round 5
// speedup vs baseline: 1.3100x; 1.0283x over previous
#include <cuda_runtime.h>
#include <cstdint>

#define N_NODES 10000
#define F_DIM   256
#define H_DIM   512
#define E_MAX   320000

// ---------------- scratch (device globals; no allocs allowed) ----------------
// NOTE: zero-initialized at module load; k_aggregate<1> re-zeroes g_cnt/g_cur
// at the end of every call so each replay starts from the same state.
__device__ float g_ax[N_NODES * F_DIM];   // aggregated X (layer-1 agg-first)
__device__ float g_h1[N_NODES * H_DIM];   // layer-1 activations (gemm1 out)
__device__ float g_c2[N_NODES * F_DIM];   // gemm2 out (pre-aggregation)
__device__ float g_dinv[N_NODES];
__device__ int   g_cnt[N_NODES];
__device__ int   g_off[N_NODES + 1];
__device__ int   g_cur[N_NODES];
__device__ int   g_csrc[E_MAX];
__device__ float g_cnorm[E_MAX];
__device__ int   g_is64;

// ---------------- small helpers ----------------
__device__ __forceinline__ uint32_t smem_u32(const void* p) {
    uint32_t a;
    asm("{ .reg .u64 t; cvta.to.shared.u64 t, %1; cvt.u32.u64 %0, t; }" : "=r"(a) : "l"(p));
    return a;
}
__device__ __forceinline__ uint32_t f2tf32(float f) {
    uint32_t u;
    asm("cvt.rna.tf32.f32 %0, %1;" : "=r"(u) : "f"(f));
    return u;
}
__device__ __forceinline__ void mma_tf32(float* d, const uint32_t* a, const uint32_t* b) {
    asm volatile(
        "mma.sync.aligned.m16n8k8.row.col.f32.tf32.tf32.f32 "
        "{%0,%1,%2,%3},{%4,%5,%6,%7},{%8,%9},{%0,%1,%2,%3};"
        : "+f"(d[0]), "+f"(d[1]), "+f"(d[2]), "+f"(d[3])
        : "r"(a[0]), "r"(a[1]), "r"(a[2]), "r"(a[3]), "r"(b[0]), "r"(b[1]));
}
__device__ __forceinline__ void cp16(uint32_t dst, const void* src, bool full) {
    int sz = full ? 16 : 0;
    asm volatile("cp.async.ca.shared.global [%0], [%1], 16, %2;"
                 :: "r"(dst), "l"(src), "r"(sz));
}
#define CP_COMMIT() asm volatile("cp.async.commit_group;" ::: "memory")
#define CP_WAIT(n)  asm volatile("cp.async.wait_group %0;" :: "n"(n) : "memory")

// ---------------- edge dtype helpers ----------------
__device__ __forceinline__ bool detect64(const void* eptr) {
    const unsigned int* w = (const unsigned int*)eptr;
    bool is64 = true;
    for (int i = 0; i < 32; i++)
        if (w[2 * i + 1] != 0u) { is64 = false; break; }
    return is64;
}
__device__ __forceinline__ int edge_dst_f(const void* eptr, int e, int E, bool is64) {
    if (is64) return (int)((const long long*)eptr)[(size_t)E + e];
    return ((const int*)eptr)[(size_t)E + e];
}
__device__ __forceinline__ void edge_sd(const void* eptr, int e, int E, int& s, int& d) {
    if (g_is64) {
        const long long* p = (const long long*)eptr;
        s = (int)p[e]; d = (int)p[(size_t)E + e];
    } else {
        const int* p = (const int*)eptr;
        s = p[e]; d = p[(size_t)E + e];
    }
}

// ---------------- preprocessing ----------------
// count + per-block dtype detect + (block 0) publish g_is64 and zero out[]
__global__ void k_count(const void* eptr, int E, float* out) {
    __shared__ int s_is64;
    if (threadIdx.x == 0) {
        bool is64 = detect64(eptr);
        s_is64 = is64 ? 1 : 0;
        if (blockIdx.x == 0) g_is64 = s_is64;
    }
    __syncthreads();
    if (blockIdx.x == 0 && threadIdx.x < F_DIM) out[threadIdx.x] = 0.0f;
    const int e = blockIdx.x * blockDim.x + threadIdx.x;
    if (e >= E) return;
    atomicAdd(&g_cnt[edge_dst_f(eptr, e, E, s_is64 != 0)], 1);
}

// fast 1-block scan: 1024 thr x 10 elems + shfl warp scans; fused dinv
__global__ void __launch_bounds__(1024) k_scan() {
    __shared__ int wsum[32];
    const int t = threadIdx.x, lane = t & 31, w = t >> 5;
    const int base = t * 10;
    int v[10], s = 0;
    #pragma unroll
    for (int j = 0; j < 10; j++) {
        int i = base + j;
        int c = 0;
        if (i < N_NODES) {
            c = g_cnt[i];
            g_dinv[i] = rsqrtf((float)c + 1.0f);
        }
        v[j] = s; s += c;
    }
    int inc = s;
    #pragma unroll
    for (int o = 1; o < 32; o <<= 1) {
        int u = __shfl_up_sync(0xffffffffu, inc, o);
        if (lane >= o) inc += u;
    }
    if (lane == 31) wsum[w] = inc;
    __syncthreads();
    if (w == 0) {
        int ws = wsum[lane];
        #pragma unroll
        for (int o = 1; o < 32; o <<= 1) {
            int u = __shfl_up_sync(0xffffffffu, ws, o);
            if (lane >= o) ws += u;
        }
        wsum[lane] = ws;
    }
    __syncthreads();
    const int tbase = ((w > 0) ? wsum[w - 1] : 0) + inc - s;
    #pragma unroll
    for (int j = 0; j < 10; j++) {
        int i = base + j;
        if (i < N_NODES) g_off[i] = tbase + v[j];
    }
    if (t == 0) g_off[N_NODES] = wsum[31];
}

__global__ void k_scatter(const void* eptr, int E) {
    int e = blockIdx.x * blockDim.x + threadIdx.x;
    if (e >= E) return;
    int s, d;
    edge_sd(eptr, e, E, s, d);
    int pos = g_off[d] + atomicAdd(&g_cur[d], 1);
    g_csrc[pos] = s;
    g_cnorm[pos] = g_dinv[s] * g_dinv[d];
}

// ---------------- tf32 mma.sync GEMM, cp.async double-buffered ----------------
// C[M,Nc] = A[M,K] @ B[K,Nc]; block tile 128x128, K-chunk 32, 8 warps (4m x 2n),
// warp tile 32x64. mode 1: A=g_ax, C=g_h1 (+bias+relu). mode 2: A=g_h1, C=g_c2.
// smem (fp32 words): As stage 128*36=4608, Bs stage 32*136=4352; two stages each.
#define AS_W 36
#define BS_W 136
#define A_STG 4608
#define B_STG 4352
#define GEMM_SMEM_BYTES ((2 * (A_STG + B_STG)) * 4)

__global__ void __launch_bounds__(256, 2) k_gemm(const float* __restrict__ Bw,
                                                 const float* __restrict__ bias,
                                                 int M, int Nc, int K, int mode) {
    extern __shared__ float sm[];
    float* AsBuf[2] = { sm, sm + A_STG };
    float* BsBuf[2] = { sm + 2 * A_STG, sm + 2 * A_STG + B_STG };
    const uint32_t smA[2] = { smem_u32(AsBuf[0]), smem_u32(AsBuf[1]) };
    const uint32_t smB[2] = { smem_u32(BsBuf[0]), smem_u32(BsBuf[1]) };

    const float* __restrict__ A = (mode == 1) ? g_ax : g_h1;
    float* __restrict__ C       = (mode == 1) ? g_h1 : g_c2;

    const int tid = threadIdx.x;
    const int lane = tid & 31, warp = tid >> 5;
    const int wm = warp >> 1, wn = warp & 1;
    const int bm = blockIdx.x * 128, bn = blockIdx.y * 128;
    const int g = lane >> 2, c = lane & 3;

    // staging maps
    const int a_row = tid >> 1;               // wrong granularity? no: see below
    // A: 128 rows x 32 words = 1024 16B-chunks; 256 thr x 4
    // chunk f: row = f>>3, c16 = (f&7)*4
    // B: 32 rows x 128 words = 1024 chunks; row = f>>5, c16 = (f&31)*4
    (void)a_row;

    float acc[2][8][4];
    #pragma unroll
    for (int mi = 0; mi < 2; mi++)
        #pragma unroll
        for (int ni = 0; ni < 8; ni++)
            #pragma unroll
            for (int j = 0; j < 4; j++) acc[mi][ni][j] = 0.0f;

    const int T = K / 32;

    auto load_stage = [&](int i, int s) {
        const int k0 = i * 32;
        #pragma unroll
        for (int j = 0; j < 4; j++) {
            const int f = tid + 256 * j;
            const int row = f >> 3, c16 = (f & 7) * 4;
            const bool ok = (bm + row) < M;
            cp16(smA[s] + (uint32_t)(row * AS_W + c16) * 4,
                 A + (size_t)(bm + row) * K + k0 + c16, ok);
        }
        #pragma unroll
        for (int j = 0; j < 4; j++) {
            const int f = tid + 256 * j;
            const int row = f >> 5, c16 = (f & 31) * 4;
            cp16(smB[s] + (uint32_t)(row * BS_W + c16) * 4,
                 Bw + (size_t)(k0 + row) * Nc + bn + c16, true);
        }
        CP_COMMIT();
    };

    load_stage(0, 0);

    const int a_base = (wm * 32 + g) * AS_W + c;
    const int b_base = c * BS_W + wn * 64 + g;

    for (int i = 0; i < T; i++) {
        const int s = i & 1;
        if (i + 1 < T) { load_stage(i + 1, s ^ 1); CP_WAIT(1); }
        else           { CP_WAIT(0); }
        __syncthreads();

        const float* Asf = AsBuf[s];
        const float* Bsf = BsBuf[s];
        #pragma unroll
        for (int k8 = 0; k8 < 4; k8++) {
            uint32_t af[2][4], bf[8][2];
            const int ak = a_base + k8 * 8;
            #pragma unroll
            for (int mi = 0; mi < 2; mi++) {
                const int o = ak + mi * (16 * AS_W);
                af[mi][0] = f2tf32(Asf[o]);
                af[mi][1] = f2tf32(Asf[o + 8 * AS_W]);
                af[mi][2] = f2tf32(Asf[o + 4]);
                af[mi][3] = f2tf32(Asf[o + 8 * AS_W + 4]);
            }
            const int bk = b_base + k8 * 8 * BS_W;
            #pragma unroll
            for (int ni = 0; ni < 8; ni++) {
                bf[ni][0] = f2tf32(Bsf[bk + ni * 8]);
                bf[ni][1] = f2tf32(Bsf[bk + 4 * BS_W + ni * 8]);
            }
            #pragma unroll
            for (int mi = 0; mi < 2; mi++)
                #pragma unroll
                for (int ni = 0; ni < 8; ni++)
                    mma_tf32(acc[mi][ni], af[mi], bf[ni]);
        }
        __syncthreads();
    }

    // epilogue
    const bool relu = (mode == 1);
    #pragma unroll
    for (int mi = 0; mi < 2; mi++) {
        const int r0 = bm + wm * 32 + mi * 16 + g;
        const int r1 = r0 + 8;
        #pragma unroll
        for (int ni = 0; ni < 8; ni++) {
            const int col = bn + wn * 64 + ni * 8 + 2 * c;
            float v0 = acc[mi][ni][0], v1 = acc[mi][ni][1];
            float v2 = acc[mi][ni][2], v3 = acc[mi][ni][3];
            if (relu) {
                const float bb0 = bias[col], bb1 = bias[col + 1];
                v0 = fmaxf(v0 + bb0, 0.f); v1 = fmaxf(v1 + bb1, 0.f);
                v2 = fmaxf(v2 + bb0, 0.f); v3 = fmaxf(v3 + bb1, 0.f);
            }
            if (r0 < M) *(float2*)(C + (size_t)r0 * Nc + col) = make_float2(v0, v1);
            if (r1 < M) *(float2*)(C + (size_t)r1 * Nc + col) = make_float2(v2, v3);
        }
    }
}

// ---------------- CSR aggregation on 256 features ----------------
// MODE 0: g_ax[n] = sum norm*xsrc[s] + dinv^2*xsrc[n]
// MODE 1: src = g_c2; fused +bias, relu, atomic max into out(256); cleanup cnt/cur
template <int MODE>
__global__ void k_aggregate(const float* __restrict__ xsrc,
                            const float* __restrict__ bias,
                            float* __restrict__ out) {
    const float* __restrict__ src = (MODE == 0) ? xsrc : (const float*)g_c2;

    const int n = blockIdx.x;
    const int tid = threadIdx.x;
    const int ccol = tid * 4;

    __shared__ int   s_src[64];
    __shared__ float s_w[64];

    float4 acc = make_float4(0.f, 0.f, 0.f, 0.f);
    const int s = g_off[n], e = g_off[n + 1];

    for (int base = s; base < e; base += 64) {
        const int cnt = min(64, e - base);
        __syncthreads();
        if (tid < cnt) {
            s_src[tid] = g_csrc[base + tid];
            s_w[tid]   = g_cnorm[base + tid];
        }
        __syncthreads();
        #pragma unroll 4
        for (int i = 0; i < cnt; i++) {
            const float4 v = *(const float4*)(src + (size_t)s_src[i] * F_DIM + ccol);
            const float w = s_w[i];
            acc.x = fmaf(w, v.x, acc.x);
            acc.y = fmaf(w, v.y, acc.y);
            acc.z = fmaf(w, v.z, acc.z);
            acc.w = fmaf(w, v.w, acc.w);
        }
    }

    const float di = g_dinv[n];
    const float w = di * di;
    const float4 v = *(const float4*)(src + (size_t)n * F_DIM + ccol);
    acc.x = fmaf(w, v.x, acc.x);
    acc.y = fmaf(w, v.y, acc.y);
    acc.z = fmaf(w, v.z, acc.z);
    acc.w = fmaf(w, v.w, acc.w);

    if (MODE == 0) {
        *(float4*)(g_ax + (size_t)n * F_DIM + ccol) = acc;
    } else {
        const float4 b = *(const float4*)(bias + ccol);
        acc.x = fmaxf(acc.x + b.x, 0.f);
        acc.y = fmaxf(acc.y + b.y, 0.f);
        acc.z = fmaxf(acc.z + b.z, 0.f);
        acc.w = fmaxf(acc.w + b.w, 0.f);
        int* o = (int*)out;
        atomicMax(o + ccol + 0, __float_as_int(acc.x));
        atomicMax(o + ccol + 1, __float_as_int(acc.y));
        atomicMax(o + ccol + 2, __float_as_int(acc.z));
        atomicMax(o + ccol + 3, __float_as_int(acc.w));
        // self-clean for next replay (deterministic across calls)
        if (tid == 0) { g_cnt[n] = 0; g_cur[n] = 0; }
    }
}

// ---------------- launch ----------------
extern "C" void kernel_launch(void* const* d_in, const int* in_sizes, int n_in,
                              void* d_out, int out_size) {
    const float* x  = (const float*)d_in[0];
    const void*  ei = d_in[1];
    const float* W1 = (const float*)d_in[2];
    const float* b1 = (const float*)d_in[3];
    const float* W2 = (const float*)d_in[4];
    const float* b2 = (const float*)d_in[5];
    float* out = (float*)d_out;

    const int E = in_sizes[1] / 2;

    static int s_attr_done = 0;
    if (!s_attr_done) {
        cudaFuncSetAttribute(k_gemm, cudaFuncAttributeMaxDynamicSharedMemorySize,
                             GEMM_SMEM_BYTES);
        s_attr_done = 1;
    }

    // g_cnt/g_cur are zero on first call (static init) and re-zeroed each call
    // by k_aggregate<1>.
    k_count<<<(E + 255) / 256, 256>>>(ei, E, out);
    k_scan<<<1, 1024>>>();
    k_scatter<<<(E + 255) / 256, 256>>>(ei, E);

    // layer 1: aggregate-first (linearity: A(XW) = (AX)W)
    k_aggregate<0><<<N_NODES, F_DIM / 4>>>(x, nullptr, nullptr);
    // h1 = relu((AX) @ W1 + b1): 10000x256 @ 256x512
    k_gemm<<<dim3((N_NODES + 127) / 128, H_DIM / 128), 256, GEMM_SMEM_BYTES>>>(
        W1, b1, N_NODES, H_DIM, F_DIM, 1);
    // layer 2: c2 = h1 @ W2: 10000x512 @ 512x256
    k_gemm<<<dim3((N_NODES + 127) / 128, F_DIM / 128), 256, GEMM_SMEM_BYTES>>>(
        W2, nullptr, N_NODES, F_DIM, H_DIM, 2);
    // aggregate + b2 + relu + fused global max pool -> out (1x256)
    k_aggregate<1><<<N_NODES, F_DIM / 4>>>(nullptr, b2, out);
}

// round 6
// speedup vs baseline: 1.3965x; 1.0660x over previous
#include <cuda_runtime.h>
#include <cuda_fp16.h>
#include <cstdint>

#define N_NODES 10000
#define F_DIM   256
#define H_DIM   512
#define E_MAX   320000

// ---------------- scratch (device globals; no allocs allowed) ----------------
// zero-initialized at load; k_agg_out re-zeroes g_cnt/g_cur each call.
__device__ __half g_xh[N_NODES * F_DIM];   // x in fp16
__device__ __half g_ax[N_NODES * F_DIM];   // aggregated X (fp16)
__device__ __half g_h1[N_NODES * H_DIM];   // layer-1 activations (fp16)
__device__ __half g_c2[N_NODES * F_DIM];   // gemm2 out (fp16)
__device__ __half g_w1t[H_DIM * F_DIM];    // W1^T [512][256] fp16 (n-major, k contig)
__device__ __half g_w2t[F_DIM * H_DIM];    // W2^T [256][512] fp16
__device__ float  g_dinv[N_NODES];
__device__ int    g_cnt[N_NODES];
__device__ int    g_off[N_NODES + 1];
__device__ int    g_cur[N_NODES];
__device__ int    g_csrc[E_MAX];
__device__ float  g_cnorm[E_MAX];
__device__ int    g_is64;

// ---------------- small helpers ----------------
__device__ __forceinline__ uint32_t smem_u32(const void* p) {
    uint32_t a;
    asm("{ .reg .u64 t; cvta.to.shared.u64 t, %1; cvt.u32.u64 %0, t; }" : "=r"(a) : "l"(p));
    return a;
}
__device__ __forceinline__ void mma_f16(float* d, const uint32_t* a, const uint32_t* b) {
    asm volatile(
        "mma.sync.aligned.m16n8k16.row.col.f32.f16.f16.f32 "
        "{%0,%1,%2,%3},{%4,%5,%6,%7},{%8,%9},{%0,%1,%2,%3};"
        : "+f"(d[0]), "+f"(d[1]), "+f"(d[2]), "+f"(d[3])
        : "r"(a[0]), "r"(a[1]), "r"(a[2]), "r"(a[3]), "r"(b[0]), "r"(b[1]));
}
__device__ __forceinline__ void cp16(uint32_t dst, const void* src, bool full) {
    int sz = full ? 16 : 0;
    asm volatile("cp.async.ca.shared.global [%0], [%1], 16, %2;"
                 :: "r"(dst), "l"(src), "r"(sz));
}
#define CP_COMMIT() asm volatile("cp.async.commit_group;" ::: "memory")
#define CP_WAIT(n)  asm volatile("cp.async.wait_group %0;" :: "n"(n) : "memory")

// ---------------- edge dtype helpers ----------------
__device__ __forceinline__ bool detect64(const void* eptr) {
    const unsigned int* w = (const unsigned int*)eptr;
    bool is64 = true;
    for (int i = 0; i < 32; i++)
        if (w[2 * i + 1] != 0u) { is64 = false; break; }
    return is64;
}
__device__ __forceinline__ int edge_dst_f(const void* eptr, int e, int E, bool is64) {
    if (is64) return (int)((const long long*)eptr)[(size_t)E + e];
    return ((const int*)eptr)[(size_t)E + e];
}
__device__ __forceinline__ void edge_sd(const void* eptr, int e, int E, int& s, int& d) {
    if (g_is64) {
        const long long* p = (const long long*)eptr;
        s = (int)p[e]; d = (int)p[(size_t)E + e];
    } else {
        const int* p = (const int*)eptr;
        s = p[e]; d = p[(size_t)E + e];
    }
}

// ---------------- preprocessing ----------------
__global__ void k_count(const void* eptr, int E, float* out) {
    __shared__ int s_is64;
    if (threadIdx.x == 0) {
        bool is64 = detect64(eptr);
        s_is64 = is64 ? 1 : 0;
        if (blockIdx.x == 0) g_is64 = s_is64;
    }
    __syncthreads();
    if (blockIdx.x == 0 && threadIdx.x < F_DIM) out[threadIdx.x] = 0.0f;
    const int e = blockIdx.x * blockDim.x + threadIdx.x;
    if (e >= E) return;
    atomicAdd(&g_cnt[edge_dst_f(eptr, e, E, s_is64 != 0)], 1);
}

__global__ void __launch_bounds__(1024) k_scan() {
    __shared__ int wsum[32];
    const int t = threadIdx.x, lane = t & 31, w = t >> 5;
    const int base = t * 10;
    int v[10], s = 0;
    #pragma unroll
    for (int j = 0; j < 10; j++) {
        int i = base + j;
        int c = 0;
        if (i < N_NODES) {
            c = g_cnt[i];
            g_dinv[i] = rsqrtf((float)c + 1.0f);
        }
        v[j] = s; s += c;
    }
    int inc = s;
    #pragma unroll
    for (int o = 1; o < 32; o <<= 1) {
        int u = __shfl_up_sync(0xffffffffu, inc, o);
        if (lane >= o) inc += u;
    }
    if (lane == 31) wsum[w] = inc;
    __syncthreads();
    if (w == 0) {
        int ws = wsum[lane];
        #pragma unroll
        for (int o = 1; o < 32; o <<= 1) {
            int u = __shfl_up_sync(0xffffffffu, ws, o);
            if (lane >= o) ws += u;
        }
        wsum[lane] = ws;
    }
    __syncthreads();
    const int tbase = ((w > 0) ? wsum[w - 1] : 0) + inc - s;
    #pragma unroll
    for (int j = 0; j < 10; j++) {
        int i = base + j;
        if (i < N_NODES) g_off[i] = tbase + v[j];
    }
    if (t == 0) g_off[N_NODES] = wsum[31];
}

__global__ void k_scatter(const void* eptr, int E) {
    int e = blockIdx.x * blockDim.x + threadIdx.x;
    if (e >= E) return;
    int s, d;
    edge_sd(eptr, e, E, s, d);
    int pos = g_off[d] + atomicAdd(&g_cur[d], 1);
    g_csrc[pos] = s;
    g_cnorm[pos] = g_dinv[s] * g_dinv[d];
}

// ---------------- conversions ----------------
// x fp32 -> g_xh fp16 (half2 per thread)
__global__ void k_cvt_x(const float* __restrict__ x) {
    const int idx = blockIdx.x * blockDim.x + threadIdx.x;  // half2 index
    const float2 f = ((const float2*)x)[idx];
    ((__half2*)g_xh)[idx] = __floats2half2_rn(f.x, f.y);
}

// W [R][C] fp32 -> Wt [C][R] fp16 (transpose + convert)
__global__ void k_cvt_w(const float* __restrict__ w, int R, int C, int which) {
    __half* outp = (which == 1) ? g_w1t : g_w2t;
    __shared__ float tile[32][33];
    const int c0 = blockIdx.x * 32, r0 = blockIdx.y * 32;
    #pragma unroll
    for (int j = 0; j < 32; j += 8)
        tile[threadIdx.y + j][threadIdx.x] =
            w[(size_t)(r0 + threadIdx.y + j) * C + c0 + threadIdx.x];
    __syncthreads();
    #pragma unroll
    for (int j = 0; j < 32; j += 8)
        outp[(size_t)(c0 + threadIdx.y + j) * R + r0 + threadIdx.x] =
            __float2half(tile[threadIdx.x][threadIdx.y + j]);
}

// ---------------- fp16 mma.sync GEMM, cp.async double-buffered ----------------
// C[M,Nc](half) = A[M,K](half) @ Bt[Nc,K](half)^T; tiles 128x128, K-chunk 32,
// 8 warps (4m x 2n), warp tile 32x64 via m16n8k16.
// mode 1: A=g_ax, Bt=g_w1t, C=g_h1 (+bias+relu). mode 2: A=g_h1, Bt=g_w2t, C=g_c2.
#define ASW 40            // halves per smem row (pad 8 -> conflict-free)
#define STG_H (128 * ASW) // halves per stage (A or B)
#define GEMM_SMEM_BYTES (4 * STG_H * 2)

__global__ void __launch_bounds__(256, 2) k_gemm(const float* __restrict__ bias,
                                                 int M, int Nc, int K, int mode) {
    extern __shared__ __half smh[];
    __half* AsB[2] = { smh, smh + STG_H };
    __half* BsB[2] = { smh + 2 * STG_H, smh + 3 * STG_H };
    const uint32_t smA[2] = { smem_u32(AsB[0]), smem_u32(AsB[1]) };
    const uint32_t smB[2] = { smem_u32(BsB[0]), smem_u32(BsB[1]) };

    const __half* __restrict__ A  = (mode == 1) ? g_ax  : g_h1;
    const __half* __restrict__ Bt = (mode == 1) ? g_w1t : g_w2t;
    __half* __restrict__ C        = (mode == 1) ? g_h1  : g_c2;

    const int tid = threadIdx.x;
    const int lane = tid & 31, warp = tid >> 5;
    const int wm = warp >> 1, wn = warp & 1;
    const int bm = blockIdx.x * 128, bn = blockIdx.y * 128;
    const int g = lane >> 2, c = lane & 3;

    float acc[2][8][4];
    #pragma unroll
    for (int mi = 0; mi < 2; mi++)
        #pragma unroll
        for (int ni = 0; ni < 8; ni++)
            #pragma unroll
            for (int j = 0; j < 4; j++) acc[mi][ni][j] = 0.0f;

    const int T = K / 32;

    auto load_stage = [&](int i, int s) {
        const int k0 = i * 32;
        // A: 128 rows x 32 halves = 64B/row = 4 x cp16; 512 chunks / 256 thr = 2
        #pragma unroll
        for (int j = 0; j < 2; j++) {
            const int f = tid + 256 * j;
            const int row = f >> 2, ch = (f & 3) * 8;    // halves
            cp16(smA[s] + (uint32_t)(row * ASW + ch) * 2,
                 A + (size_t)(bm + row) * K + k0 + ch, (bm + row) < M);
        }
        #pragma unroll
        for (int j = 0; j < 2; j++) {
            const int f = tid + 256 * j;
            const int row = f >> 2, ch = (f & 3) * 8;
            cp16(smB[s] + (uint32_t)(row * ASW + ch) * 2,
                 Bt + (size_t)(bn + row) * K + k0 + ch, true);
        }
        CP_COMMIT();
    };

    load_stage(0, 0);

    // fragment bases in half2 units (ASW/2 = 20 per row)
    const int a_base = (wm * 32 + g) * 20 + c;
    const int b_base = (wn * 64 + g) * 20 + c;

    for (int i = 0; i < T; i++) {
        const int s = i & 1;
        if (i + 1 < T) { load_stage(i + 1, s ^ 1); CP_WAIT(1); }
        else           { CP_WAIT(0); }
        __syncthreads();

        const uint32_t* As32 = (const uint32_t*)AsB[s];
        const uint32_t* Bs32 = (const uint32_t*)BsB[s];
        #pragma unroll
        for (int q = 0; q < 2; q++) {              // two k16 per 32-chunk
            const int qo = q * 8;                  // half2 offset
            uint32_t af[2][4], bf[8][2];
            #pragma unroll
            for (int mi = 0; mi < 2; mi++) {
                const int o = a_base + mi * (16 * 20) + qo;
                af[mi][0] = As32[o];
                af[mi][1] = As32[o + 8 * 20];
                af[mi][2] = As32[o + 4];
                af[mi][3] = As32[o + 8 * 20 + 4];
            }
            #pragma unroll
            for (int ni = 0; ni < 8; ni++) {
                const int o = b_base + ni * (8 * 20) + qo;
                bf[ni][0] = Bs32[o];
                bf[ni][1] = Bs32[o + 4];
            }
            #pragma unroll
            for (int mi = 0; mi < 2; mi++)
                #pragma unroll
                for (int ni = 0; ni < 8; ni++)
                    mma_f16(acc[mi][ni], af[mi], bf[ni]);
        }
        __syncthreads();
    }

    // epilogue: half2 stores
    const bool relu = (mode == 1);
    #pragma unroll
    for (int mi = 0; mi < 2; mi++) {
        const int r0 = bm + wm * 32 + mi * 16 + g;
        const int r1 = r0 + 8;
        #pragma unroll
        for (int ni = 0; ni < 8; ni++) {
            const int col = bn + wn * 64 + ni * 8 + 2 * c;
            float v0 = acc[mi][ni][0], v1 = acc[mi][ni][1];
            float v2 = acc[mi][ni][2], v3 = acc[mi][ni][3];
            if (relu) {
                const float bb0 = bias[col], bb1 = bias[col + 1];
                v0 = fmaxf(v0 + bb0, 0.f); v1 = fmaxf(v1 + bb1, 0.f);
                v2 = fmaxf(v2 + bb0, 0.f); v3 = fmaxf(v3 + bb1, 0.f);
            }
            if (r0 < M) *(__half2*)(C + (size_t)r0 * Nc + col) = __floats2half2_rn(v0, v1);
            if (r1 < M) *(__half2*)(C + (size_t)r1 * Nc + col) = __floats2half2_rn(v2, v3);
        }
    }
}

// ---------------- CSR aggregation on 256 fp16 features ----------------
// IN:  g_ax[n] = sum norm*g_xh[s] + dinv^2*g_xh[n]   (fp32 accum, fp16 out)
// OUT: gather g_c2, +bias, relu, atomicMax into out(256 fp32); cleanup cnt/cur
template <int MODE>
__global__ void k_agg(const float* __restrict__ bias, float* __restrict__ out) {
    const __half* __restrict__ src = (MODE == 0) ? g_xh : g_c2;

    const int n = blockIdx.x;
    const int tid = threadIdx.x;
    const int ccol = tid * 4;          // halves

    __shared__ int   s_src[64];
    __shared__ float s_w[64];

    float4 acc = make_float4(0.f, 0.f, 0.f, 0.f);
    const int s = g_off[n], e = g_off[n + 1];

    for (int base = s; base < e; base += 64) {
        const int cnt = min(64, e - base);
        __syncthreads();
        if (tid < cnt) {
            s_src[tid] = g_csrc[base + tid];
            s_w[tid]   = g_cnorm[base + tid];
        }
        __syncthreads();
        #pragma unroll 4
        for (int i = 0; i < cnt; i++) {
            const uint2 raw = *(const uint2*)(src + (size_t)s_src[i] * F_DIM + ccol);
            const float2 f0 = __half22float2(*(const __half2*)&raw.x);
            const float2 f1 = __half22float2(*(const __half2*)&raw.y);
            const float w = s_w[i];
            acc.x = fmaf(w, f0.x, acc.x);
            acc.y = fmaf(w, f0.y, acc.y);
            acc.z = fmaf(w, f1.x, acc.z);
            acc.w = fmaf(w, f1.y, acc.w);
        }
    }

    const float di = g_dinv[n];
    const float w = di * di;
    {
        const uint2 raw = *(const uint2*)(src + (size_t)n * F_DIM + ccol);
        const float2 f0 = __half22float2(*(const __half2*)&raw.x);
        const float2 f1 = __half22float2(*(const __half2*)&raw.y);
        acc.x = fmaf(w, f0.x, acc.x);
        acc.y = fmaf(w, f0.y, acc.y);
        acc.z = fmaf(w, f1.x, acc.z);
        acc.w = fmaf(w, f1.y, acc.w);
    }

    if (MODE == 0) {
        uint2 o;
        *(__half2*)&o.x = __floats2half2_rn(acc.x, acc.y);
        *(__half2*)&o.y = __floats2half2_rn(acc.z, acc.w);
        *(uint2*)(g_ax + (size_t)n * F_DIM + ccol) = o;
    } else {
        const float4 b = *(const float4*)(bias + ccol);
        acc.x = fmaxf(acc.x + b.x, 0.f);
        acc.y = fmaxf(acc.y + b.y, 0.f);
        acc.z = fmaxf(acc.z + b.z, 0.f);
        acc.w = fmaxf(acc.w + b.w, 0.f);
        // post-ReLU values >= 0, so int ordering == float ordering
        int* o = (int*)out;
        atomicMax(o + ccol + 0, __float_as_int(acc.x));
        atomicMax(o + ccol + 1, __float_as_int(acc.y));
        atomicMax(o + ccol + 2, __float_as_int(acc.z));
        atomicMax(o + ccol + 3, __float_as_int(acc.w));
        if (tid == 0) { g_cnt[n] = 0; g_cur[n] = 0; }   // self-clean for replay
    }
}

// ---------------- launch ----------------
extern "C" void kernel_launch(void* const* d_in, const int* in_sizes, int n_in,
                              void* d_out, int out_size) {
    const float* x  = (const float*)d_in[0];
    const void*  ei = d_in[1];
    const float* W1 = (const float*)d_in[2];
    const float* b1 = (const float*)d_in[3];
    const float* W2 = (const float*)d_in[4];
    const float* b2 = (const float*)d_in[5];
    float* out = (float*)d_out;

    const int E = in_sizes[1] / 2;

    static int s_attr_done = 0;
    if (!s_attr_done) {
        cudaFuncSetAttribute(k_gemm, cudaFuncAttributeMaxDynamicSharedMemorySize,
                             GEMM_SMEM_BYTES);
        s_attr_done = 1;
    }

    k_count<<<(E + 255) / 256, 256>>>(ei, E, out);
    k_scan<<<1, 1024>>>();
    k_scatter<<<(E + 255) / 256, 256>>>(ei, E);

    // fp16 conversions
    k_cvt_x<<<N_NODES * F_DIM / 2 / 256, 256>>>(x);
    k_cvt_w<<<dim3(H_DIM / 32, F_DIM / 32), dim3(32, 8)>>>(W1, F_DIM, H_DIM, 1);
    k_cvt_w<<<dim3(F_DIM / 32, H_DIM / 32), dim3(32, 8)>>>(W2, H_DIM, F_DIM, 2);

    // layer 1: aggregate-first (linearity: A(XW) = (AX)W)
    k_agg<0><<<N_NODES, 64>>>(nullptr, nullptr);
    // h1 = relu((AX) @ W1 + b1): 10000x256 @ 256x512
    k_gemm<<<dim3((N_NODES + 127) / 128, H_DIM / 128), 256, GEMM_SMEM_BYTES>>>(
        b1, N_NODES, H_DIM, F_DIM, 1);
    // layer 2: c2 = h1 @ W2: 10000x512 @ 512x256
    k_gemm<<<dim3((N_NODES + 127) / 128, F_DIM / 128), 256, GEMM_SMEM_BYTES>>>(
        nullptr, N_NODES, F_DIM, H_DIM, 2);
    // aggregate + b2 + relu + fused global max pool -> out (1x256)
    k_agg<1><<<N_NODES, 64>>>(b2, out);
}